// round 1
// baseline (speedup 1.0000x reference)
#include <cuda_runtime.h>

// Problem collapse:
//   reference out = 2048 * (x @ Wv^T + bv) @ Wp^T + bp
// because einsum('bhqk,bhvo->bhvo', attn, v) = v * sum(attn) and softmax rows
// sum to 1 => sum(attn) = S = 2048 exactly. Q/K path is dead code.
//
// Plan:
//   Wc    = Wp @ Wv                      (1024x1024x1024 GEMM)
//   bcomb = 2048 * Wp @ bv + bp          (matvec)
//   out   = 2048 * x @ Wc^T + bcomb      (8192x1024x1024 GEMM)

#define BM 128
#define BN 128
#define BK 16

__device__ float g_Wc[1024 * 1024];
__device__ float g_bcomb[1024];

// ---------------------------------------------------------------------------
// bcomb[i] = 2048 * dot(Wp[i,:], bv) + bp[i]
// ---------------------------------------------------------------------------
__global__ __launch_bounds__(256) void bias_combine_kernel(
    const float* __restrict__ Wp, const float* __restrict__ bv,
    const float* __restrict__ bp)
{
    __shared__ float red[256];
    int i = blockIdx.x;
    float s = 0.f;
    for (int j = threadIdx.x; j < 1024; j += 256)
        s += Wp[i * 1024 + j] * bv[j];
    red[threadIdx.x] = s;
    __syncthreads();
    #pragma unroll
    for (int off = 128; off > 0; off >>= 1) {
        if (threadIdx.x < off) red[threadIdx.x] += red[threadIdx.x + off];
        __syncthreads();
    }
    if (threadIdx.x == 0) g_bcomb[i] = 2048.0f * red[0] + bp[i];
}

// ---------------------------------------------------------------------------
// Wc = Wp @ Wv   (NN GEMM, M=N=K=1024, both row-major)
// ---------------------------------------------------------------------------
__global__ __launch_bounds__(256) void wc_gemm_kernel(
    const float* __restrict__ Wp, const float* __restrict__ Wv)
{
    const int K = 1024, N = 1024;
    __shared__ float As[BK][BM + 4];
    __shared__ float Bs[BK][BN + 4];

    int tid = threadIdx.x;
    int bm = blockIdx.y * BM;
    int bn = blockIdx.x * BN;
    int tm = tid >> 4;   // 0..15
    int tn = tid & 15;   // 0..15

    float acc[8][8];
    #pragma unroll
    for (int i = 0; i < 8; i++)
        #pragma unroll
        for (int j = 0; j < 8; j++) acc[i][j] = 0.f;

    for (int kt = 0; kt < K; kt += BK) {
        // A tile (Wp): 128 rows x 16 cols, store transposed As[k][m]
        #pragma unroll
        for (int i = 0; i < 2; i++) {
            int f = tid + i * 256;
            int r = f >> 2, c4 = f & 3;
            float4 v = *(const float4*)(Wp + (size_t)(bm + r) * K + kt + c4 * 4);
            As[c4 * 4 + 0][r] = v.x;
            As[c4 * 4 + 1][r] = v.y;
            As[c4 * 4 + 2][r] = v.z;
            As[c4 * 4 + 3][r] = v.w;
        }
        // B tile (Wv): 16 rows x 128 cols, n-contiguous -> Bs[k][n] direct
        #pragma unroll
        for (int i = 0; i < 2; i++) {
            int f = tid + i * 256;
            int r = f >> 5, c4 = f & 31;
            *(float4*)&Bs[r][c4 * 4] =
                *(const float4*)(Wv + (size_t)(kt + r) * N + bn + c4 * 4);
        }
        __syncthreads();

        #pragma unroll
        for (int k = 0; k < BK; k++) {
            float a[8], b[8];
            *(float4*)&a[0] = *(float4*)&As[k][tm * 8];
            *(float4*)&a[4] = *(float4*)&As[k][tm * 8 + 4];
            *(float4*)&b[0] = *(float4*)&Bs[k][tn * 8];
            *(float4*)&b[4] = *(float4*)&Bs[k][tn * 8 + 4];
            #pragma unroll
            for (int i = 0; i < 8; i++)
                #pragma unroll
                for (int j = 0; j < 8; j++)
                    acc[i][j] += a[i] * b[j];
        }
        __syncthreads();
    }

    #pragma unroll
    for (int i = 0; i < 8; i++) {
        int m = bm + tm * 8 + i;
        *(float4*)&g_Wc[(size_t)m * N + bn + tn * 8] =
            make_float4(acc[i][0], acc[i][1], acc[i][2], acc[i][3]);
        *(float4*)&g_Wc[(size_t)m * N + bn + tn * 8 + 4] =
            make_float4(acc[i][4], acc[i][5], acc[i][6], acc[i][7]);
    }
}

// ---------------------------------------------------------------------------
// out = 2048 * X @ Wc^T + bcomb    (NT GEMM, M=8192, N=K=1024)
// X row-major [M,K]; Wc row-major [N,K] (so B^T contraction is K-contiguous)
// ---------------------------------------------------------------------------
__global__ __launch_bounds__(256) void out_gemm_kernel(
    const float* __restrict__ X, float* __restrict__ C)
{
    const int K = 1024, N = 1024;
    __shared__ float As[BK][BM + 4];
    __shared__ float Bs[BK][BN + 4];

    int tid = threadIdx.x;
    int bm = blockIdx.y * BM;
    int bn = blockIdx.x * BN;
    int tm = tid >> 4;
    int tn = tid & 15;

    float acc[8][8];
    #pragma unroll
    for (int i = 0; i < 8; i++)
        #pragma unroll
        for (int j = 0; j < 8; j++) acc[i][j] = 0.f;

    for (int kt = 0; kt < K; kt += BK) {
        // A tile (X): rows m, cols k -> As[k][m]
        #pragma unroll
        for (int i = 0; i < 2; i++) {
            int f = tid + i * 256;
            int r = f >> 2, c4 = f & 3;
            float4 v = *(const float4*)(X + (size_t)(bm + r) * K + kt + c4 * 4);
            As[c4 * 4 + 0][r] = v.x;
            As[c4 * 4 + 1][r] = v.y;
            As[c4 * 4 + 2][r] = v.z;
            As[c4 * 4 + 3][r] = v.w;
        }
        // B tile (Wc, [N,K] row-major): rows n, cols k -> Bs[k][n]
        #pragma unroll
        for (int i = 0; i < 2; i++) {
            int f = tid + i * 256;
            int r = f >> 2, c4 = f & 3;
            float4 v = *(const float4*)(g_Wc + (size_t)(bn + r) * K + kt + c4 * 4);
            Bs[c4 * 4 + 0][r] = v.x;
            Bs[c4 * 4 + 1][r] = v.y;
            Bs[c4 * 4 + 2][r] = v.z;
            Bs[c4 * 4 + 3][r] = v.w;
        }
        __syncthreads();

        #pragma unroll
        for (int k = 0; k < BK; k++) {
            float a[8], b[8];
            *(float4*)&a[0] = *(float4*)&As[k][tm * 8];
            *(float4*)&a[4] = *(float4*)&As[k][tm * 8 + 4];
            *(float4*)&b[0] = *(float4*)&Bs[k][tn * 8];
            *(float4*)&b[4] = *(float4*)&Bs[k][tn * 8 + 4];
            #pragma unroll
            for (int i = 0; i < 8; i++)
                #pragma unroll
                for (int j = 0; j < 8; j++)
                    acc[i][j] += a[i] * b[j];
        }
        __syncthreads();
    }

    const float alpha = 2048.0f;
    float bb[8];
    #pragma unroll
    for (int j = 0; j < 8; j++) bb[j] = g_bcomb[bn + tn * 8 + j];

    #pragma unroll
    for (int i = 0; i < 8; i++) {
        int m = bm + tm * 8 + i;
        float4 r0 = make_float4(alpha * acc[i][0] + bb[0],
                                alpha * acc[i][1] + bb[1],
                                alpha * acc[i][2] + bb[2],
                                alpha * acc[i][3] + bb[3]);
        float4 r1 = make_float4(alpha * acc[i][4] + bb[4],
                                alpha * acc[i][5] + bb[5],
                                alpha * acc[i][6] + bb[6],
                                alpha * acc[i][7] + bb[7]);
        *(float4*)&C[(size_t)m * N + bn + tn * 8] = r0;
        *(float4*)&C[(size_t)m * N + bn + tn * 8 + 4] = r1;
    }
}

// ---------------------------------------------------------------------------
extern "C" void kernel_launch(void* const* d_in, const int* in_sizes, int n_in,
                              void* d_out, int out_size)
{
    // metadata order: x, Wq, bq, Wk, bk, Wv, bv, Wp, bp
    const float* x  = (const float*)d_in[0];
    const float* Wv = (const float*)d_in[5];
    const float* bv = (const float*)d_in[6];
    const float* Wp = (const float*)d_in[7];
    const float* bp = (const float*)d_in[8];
    float* out = (float*)d_out;

    // M = B*S = 8192, N = K = D = 1024
    bias_combine_kernel<<<1024, 256>>>(Wp, bv, bp);
    wc_gemm_kernel<<<dim3(8, 8), 256>>>(Wp, Wv);
    out_gemm_kernel<<<dim3(8, 64), 256>>>(x, out);
}

// round 4
// speedup vs baseline: 2.0611x; 2.0611x over previous
#include <cuda_runtime.h>
#include <cuda_bf16.h>
#include <cstdint>

// ============================================================================
// Collapse (verified R1, rel_err 1e-6):
//   out = 2048 * x @ (Wp@Wv)^T + (2048*Wp@bv + bp)
// tcgen05 unavailable (harness PTX target = base sm_103). HMMA mma.sync path.
//
// 3-product bf16 split over K' = 3K = 3072:
//   A' = [hi(A) | hi(A) | lo(A)],  B' = [hi(B) | lo(B) | hi(B)]
//   bf16 GEMM over K' computes hi*hi + hi*lo + lo*hi with fp32 accum.
//
// R3 fix: prefetch stage buffer index was kt % STAGES (the buffer being
// consumed THIS iteration) -> data race -> NaN. Must be (kt+STAGES-1) % STAGES.
// ============================================================================

#define KDIM 1024
#define KP   3072
#define MMAIN 8192
#define NMAIN 1024

#define BM 128
#define BN 128
#define BK 64              // bf16 per k-tile (128 B per row)
#define STAGES 3
#define STAGE_BYTES (2 * BM * BK * 2)     // A tile 16KB + B tile 16KB = 32KB
#define SMEM_TOTAL (STAGES * STAGE_BYTES)

// -------------------- scratch (device globals; no allocation) ---------------
__device__ __nv_bfloat16 g_xs[(size_t)MMAIN * KP];   // split x    [hi|hi|lo]
__device__ __nv_bfloat16 g_wps[(size_t)KDIM * KP];   // split Wp   [hi|hi|lo]
__device__ __nv_bfloat16 g_wvts[(size_t)KDIM * KP];  // split Wv^T [hi|lo|hi]
__device__ __nv_bfloat16 g_wcs[(size_t)KDIM * KP];   // split Wc   [hi|lo|hi]
__device__ float g_bcomb[KDIM];

// -------------------- helpers ------------------------------------------------
__device__ __forceinline__ uint32_t sptr(const void* p) {
    return (uint32_t)__cvta_generic_to_shared(p);
}
__device__ __forceinline__ void cp_async16(uint32_t smem, const void* gmem) {
    asm volatile("cp.async.cg.shared.global [%0], [%1], 16;"
                 :: "r"(smem), "l"(gmem) : "memory");
}
__device__ __forceinline__ void cp_commit() {
    asm volatile("cp.async.commit_group;" ::: "memory");
}
template <int N> __device__ __forceinline__ void cp_wait() {
    asm volatile("cp.async.wait_group %0;" :: "n"(N) : "memory");
}
__device__ __forceinline__ void ldmatrix4(uint32_t* r, uint32_t addr) {
    asm volatile("ldmatrix.sync.aligned.m8n8.x4.shared.b16 {%0,%1,%2,%3}, [%4];"
                 : "=r"(r[0]), "=r"(r[1]), "=r"(r[2]), "=r"(r[3]) : "r"(addr));
}
__device__ __forceinline__ void mma16816(float* c, const uint32_t* a,
                                         uint32_t b0, uint32_t b1) {
    asm volatile(
        "mma.sync.aligned.m16n8k16.row.col.f32.bf16.bf16.f32 "
        "{%0,%1,%2,%3}, {%4,%5,%6,%7}, {%8,%9}, {%0,%1,%2,%3};"
        : "+f"(c[0]), "+f"(c[1]), "+f"(c[2]), "+f"(c[3])
        : "r"(a[0]), "r"(a[1]), "r"(a[2]), "r"(a[3]), "r"(b0), "r"(b1));
}
__device__ __forceinline__ void split2(float v, __nv_bfloat16& hi, __nv_bfloat16& lo) {
    hi = __float2bfloat16(v);
    lo = __float2bfloat16(v - __bfloat162float(hi));
}
// swizzled byte offset of (row, 16B-chunk c) inside a [rows x 128B] tile
__device__ __forceinline__ uint32_t swz(int row, int c) {
    return (uint32_t)(row * 128 + ((c ^ (row & 7)) << 4));
}

// -------------------- small prep kernels ------------------------------------
__global__ __launch_bounds__(256) void bias_combine_kernel(
    const float* __restrict__ Wp, const float* __restrict__ bv,
    const float* __restrict__ bp)
{
    int row = blockIdx.x * 8 + (threadIdx.x >> 5);
    int lane = threadIdx.x & 31;
    float s = 0.f;
    for (int j = lane * 4; j < KDIM; j += 128) {
        float4 w = *(const float4*)(Wp + (size_t)row * KDIM + j);
        float4 b = *(const float4*)(bv + j);
        s += w.x * b.x + w.y * b.y + w.z * b.z + w.w * b.w;
    }
#pragma unroll
    for (int o = 16; o > 0; o >>= 1) s += __shfl_xor_sync(0xffffffff, s, o);
    if (lane == 0) g_bcomb[row] = 2048.0f * s + bp[row];
}

// A-style split [hi|hi|lo] for row-major [rows,1024] fp32
__global__ __launch_bounds__(256) void splitA_kernel(
    const float* __restrict__ src, __nv_bfloat16* __restrict__ dst, int rows)
{
    int idx = blockIdx.x * blockDim.x + threadIdx.x;
    int total = rows * (KDIM / 2);
    if (idx >= total) return;
    int r = idx / (KDIM / 2);
    int k = (idx - r * (KDIM / 2)) * 2;
    float2 v = *(const float2*)(src + (size_t)r * KDIM + k);
    __nv_bfloat16 h0, l0, h1, l1;
    split2(v.x, h0, l0);
    split2(v.y, h1, l1);
    __nv_bfloat162 hh; hh.x = h0; hh.y = h1;
    __nv_bfloat162 ll; ll.x = l0; ll.y = l1;
    __nv_bfloat16* row = dst + (size_t)r * KP;
    *(__nv_bfloat162*)(row + k) = hh;
    *(__nv_bfloat162*)(row + KDIM + k) = hh;
    *(__nv_bfloat162*)(row + 2 * KDIM + k) = ll;
}

// Wv [K,N] -> split(Wv^T) [N,3K] B-style [hi|lo|hi]
__global__ __launch_bounds__(256) void wv_transpose_split_kernel(
    const float* __restrict__ Wv, __nv_bfloat16* __restrict__ dst)
{
    __shared__ float t[32][33];
    int bx = blockIdx.x * 32;
    int by = blockIdx.y * 32;
    int tx = threadIdx.x & 31, ty = threadIdx.x >> 5;
#pragma unroll
    for (int i = 0; i < 32; i += 8)
        t[ty + i][tx] = Wv[(size_t)(by + ty + i) * KDIM + bx + tx];
    __syncthreads();
#pragma unroll
    for (int i = 0; i < 32; i += 8) {
        float v = t[tx][ty + i];
        __nv_bfloat16 hi, lo;
        split2(v, hi, lo);
        __nv_bfloat16* row = dst + (size_t)(bx + ty + i) * KP;
        row[by + tx] = hi;
        row[KDIM + by + tx] = lo;
        row[2 * KDIM + by + tx] = hi;
    }
}

// -------------------- HMMA NT GEMM -------------------------------------------
// C[M,N] = A[M,K'] @ B[N,K']^T, bf16 in / fp32 acc.
// 256 thr = 8 warps: wm = wid&3 (32-row strip), wn = wid>>2 (64-col strip).
// MODE 0: epilogue -> split(Wc) [hi|lo|hi] into Bsplit.
// MODE 1: epilogue -> 2048*acc + g_bcomb[n] into Cout.
template <int MODE>
__global__ __launch_bounds__(256, 1) void hmma_gemm_kernel(
    const __nv_bfloat16* __restrict__ A, const __nv_bfloat16* __restrict__ B,
    float* __restrict__ Cout, __nv_bfloat16* __restrict__ Bsplit)
{
    extern __shared__ char smem[];
    const uint32_t sbase = sptr(smem);

    const int tid = threadIdx.x;
    const int wid = tid >> 5, lane = tid & 31;
    const int wm = wid & 3, wn = wid >> 2;
    const int bm = blockIdx.y * BM, bn = blockIdx.x * BN;

    float acc[2][8][4];
#pragma unroll
    for (int i = 0; i < 2; i++)
#pragma unroll
        for (int j = 0; j < 8; j++)
#pragma unroll
            for (int q = 0; q < 4; q++) acc[i][j][q] = 0.f;

    // --- stage loader: k-tile t -> stage buffer s ---
    auto load_stage = [&](int t, int s) {
        uint32_t sa = sbase + s * STAGE_BYTES;          // A: 128 x 128B
        uint32_t sb = sa + BM * 128;                    // B: 128 x 128B
        int kcol = t * BK;
#pragma unroll
        for (int i = 0; i < 4; i++) {
            int chunk = tid + i * 256;                  // 0..1023
            int r = chunk >> 3, c = chunk & 7;
            uint32_t sw = swz(r, c);
            cp_async16(sa + sw, A + (size_t)(bm + r) * KP + kcol + c * 8);
            cp_async16(sb + sw, B + (size_t)(bn + r) * KP + kcol + c * 8);
        }
    };

    const int NT = KP / BK;  // 48
#pragma unroll
    for (int t = 0; t < STAGES - 1; t++) { load_stage(t, t); cp_commit(); }

    // ldmatrix lane geometry (shared by A and B tiles)
    const int lrow = (lane & 7) + ((lane >> 3) & 1) * 8;  // row within 16
    const int lcol = lane >> 4;                            // 16B chunk sel (0/1)

    for (int kt = 0; kt < NT; kt++) {
        cp_wait<STAGES - 2>();   // tile kt resident
        __syncthreads();         // everyone done reading buffer (kt-1)%STAGES
        // prefetch tile kt+STAGES-1 into ITS OWN ring slot (the buffer that
        // was consumed in iteration kt-1). R3 fix: was kt % STAGES (= live
        // buffer of tile kt) -> race.
        if (kt + STAGES - 1 < NT)
            load_stage(kt + STAGES - 1, (kt + STAGES - 1) % STAGES);
        cp_commit();

        uint32_t sa = sbase + (kt % STAGES) * STAGE_BYTES;
        uint32_t sb = sa + BM * 128;

#pragma unroll
        for (int s = 0; s < BK / 16; s++) {  // 4 k16 steps
            uint32_t afr[2][4], bfr[4][4];
#pragma unroll
            for (int im = 0; im < 2; im++)
                ldmatrix4(afr[im], sa + swz(wm * 32 + im * 16 + lrow,
                                            s * 2 + lcol));
#pragma unroll
            for (int jn = 0; jn < 4; jn++)
                ldmatrix4(bfr[jn], sb + swz(wn * 64 + jn * 16 + lrow,
                                            s * 2 + lcol));
#pragma unroll
            for (int im = 0; im < 2; im++)
#pragma unroll
                for (int n8 = 0; n8 < 8; n8++) {
                    int jn = n8 >> 1, h = n8 & 1;
                    mma16816(acc[im][n8], afr[im], bfr[jn][h], bfr[jn][h + 2]);
                }
        }
        __syncthreads();
    }

    // --- epilogue: straight from registers ---
    const int qr = lane >> 2, qc = lane & 3;  // quad row / col
#pragma unroll
    for (int im = 0; im < 2; im++) {
        int m0 = bm + wm * 32 + im * 16 + qr;
#pragma unroll
        for (int n8 = 0; n8 < 8; n8++) {
            int n0 = bn + wn * 64 + n8 * 8 + qc * 2;
            float* c = acc[im][n8];
            if (MODE == 1) {
                float b0 = g_bcomb[n0], b1 = g_bcomb[n0 + 1];
                *(float2*)(Cout + (size_t)m0 * NMAIN + n0) =
                    make_float2(2048.f * c[0] + b0, 2048.f * c[1] + b1);
                *(float2*)(Cout + (size_t)(m0 + 8) * NMAIN + n0) =
                    make_float2(2048.f * c[2] + b0, 2048.f * c[3] + b1);
            } else {
#pragma unroll
                for (int q = 0; q < 4; q++) {
                    int m = m0 + (q >> 1) * 8;      // Wc row (= main-B N idx)
                    int n = n0 + (q & 1);           // Wc col (= main-B K idx)
                    __nv_bfloat16 hi, lo;
                    split2(c[q], hi, lo);
                    size_t base = (size_t)m * KP + n;
                    Bsplit[base] = hi;
                    Bsplit[base + KDIM] = lo;
                    Bsplit[base + 2 * KDIM] = hi;
                }
            }
        }
    }
}

// -------------------- host ----------------------------------------------------
extern "C" void kernel_launch(void* const* d_in, const int* in_sizes, int n_in,
                              void* d_out, int out_size)
{
    // metadata order: x, Wq, bq, Wk, bk, Wv, bv, Wp, bp
    const float* x  = (const float*)d_in[0];
    const float* Wv = (const float*)d_in[5];
    const float* bv = (const float*)d_in[6];
    const float* Wp = (const float*)d_in[7];
    const float* bp = (const float*)d_in[8];
    float* out = (float*)d_out;

    __nv_bfloat16 *xs, *wps, *wvts, *wcs;
    cudaGetSymbolAddress((void**)&xs, g_xs);
    cudaGetSymbolAddress((void**)&wps, g_wps);
    cudaGetSymbolAddress((void**)&wvts, g_wvts);
    cudaGetSymbolAddress((void**)&wcs, g_wcs);

    cudaFuncSetAttribute(hmma_gemm_kernel<0>,
                         cudaFuncAttributeMaxDynamicSharedMemorySize, SMEM_TOTAL);
    cudaFuncSetAttribute(hmma_gemm_kernel<1>,
                         cudaFuncAttributeMaxDynamicSharedMemorySize, SMEM_TOTAL);

    bias_combine_kernel<<<128, 256>>>(Wp, bv, bp);
    splitA_kernel<<<(MMAIN * (KDIM / 2) + 255) / 256, 256>>>(x, xs, MMAIN);
    splitA_kernel<<<(KDIM * (KDIM / 2) + 255) / 256, 256>>>(Wp, wps, KDIM);
    wv_transpose_split_kernel<<<dim3(32, 32), 256>>>(Wv, wvts);

    // Wc = Wp @ Wv  (epilogue emits split(Wc) for the main GEMM's B)
    hmma_gemm_kernel<0><<<dim3(8, 8), 256, SMEM_TOTAL>>>(wps, wvts, nullptr, wcs);
    // out = 2048 * x @ Wc^T + bcomb
    hmma_gemm_kernel<1><<<dim3(8, 64), 256, SMEM_TOTAL>>>(xs, wcs, out, nullptr);
}

// round 5
// speedup vs baseline: 2.1964x; 1.0656x over previous
#include <cuda_runtime.h>
#include <cuda_bf16.h>
#include <cstdint>

// ============================================================================
// Collapse (verified): out = 2048 * x @ (Wp@Wv)^T + (2048*Wp@bv + bp)
// HMMA mma.sync bf16 path (tcgen05 rejected by harness's base-sm_103 PTX).
//
// R5: compact 2-array split (hi, lo stored separately, K=1024 each) and a
// 3-product k-loop that reuses register fragments:
//   per 64-wide k-tile, load Ahi/Alo/Bhi/Blo tiles once, compute
//   acc += ahi*bhi + ahi*blo + alo*bhi   (the lo*lo term is ~2^-18, dropped)
// vs R4's [hi|hi|lo] x [hi|lo|hi] K'=3072 layout: -33% gmem traffic,
// -33% ldmatrix traffic, same MMA count. One __syncthreads per k-tile.
// ============================================================================

#define KDIM 1024
#define MMAIN 8192
#define NMAIN 1024

#define BM 128
#define BN 128
#define BK 64
#define STAGES 3
// stage: Ahi 16KB | Alo 16KB | Bhi 16KB | Blo 16KB
#define STAGE_BYTES 65536
#define SMEM_TOTAL (STAGES * STAGE_BYTES)   // 192 KB

// -------------------- scratch (device globals) -------------------------------
__device__ __nv_bfloat16 g_xhi[(size_t)MMAIN * KDIM];
__device__ __nv_bfloat16 g_xlo[(size_t)MMAIN * KDIM];
__device__ __nv_bfloat16 g_wphi[(size_t)KDIM * KDIM];
__device__ __nv_bfloat16 g_wplo[(size_t)KDIM * KDIM];
__device__ __nv_bfloat16 g_wvthi[(size_t)KDIM * KDIM];
__device__ __nv_bfloat16 g_wvtlo[(size_t)KDIM * KDIM];
__device__ __nv_bfloat16 g_wchi[(size_t)KDIM * KDIM];
__device__ __nv_bfloat16 g_wclo[(size_t)KDIM * KDIM];
__device__ float g_bcomb[KDIM];

// -------------------- helpers -------------------------------------------------
__device__ __forceinline__ uint32_t sptr(const void* p) {
    return (uint32_t)__cvta_generic_to_shared(p);
}
__device__ __forceinline__ void cp_async16(uint32_t smem, const void* gmem) {
    asm volatile("cp.async.cg.shared.global [%0], [%1], 16;"
                 :: "r"(smem), "l"(gmem) : "memory");
}
__device__ __forceinline__ void cp_commit() {
    asm volatile("cp.async.commit_group;" ::: "memory");
}
template <int N> __device__ __forceinline__ void cp_wait() {
    asm volatile("cp.async.wait_group %0;" :: "n"(N) : "memory");
}
__device__ __forceinline__ void ldmatrix4(uint32_t* r, uint32_t addr) {
    asm volatile("ldmatrix.sync.aligned.m8n8.x4.shared.b16 {%0,%1,%2,%3}, [%4];"
                 : "=r"(r[0]), "=r"(r[1]), "=r"(r[2]), "=r"(r[3]) : "r"(addr));
}
__device__ __forceinline__ void mma16816(float* c, const uint32_t* a,
                                         uint32_t b0, uint32_t b1) {
    asm volatile(
        "mma.sync.aligned.m16n8k16.row.col.f32.bf16.bf16.f32 "
        "{%0,%1,%2,%3}, {%4,%5,%6,%7}, {%8,%9}, {%0,%1,%2,%3};"
        : "+f"(c[0]), "+f"(c[1]), "+f"(c[2]), "+f"(c[3])
        : "r"(a[0]), "r"(a[1]), "r"(a[2]), "r"(a[3]), "r"(b0), "r"(b1));
}
__device__ __forceinline__ void split2(float v, __nv_bfloat16& hi, __nv_bfloat16& lo) {
    hi = __float2bfloat16(v);
    lo = __float2bfloat16(v - __bfloat162float(hi));
}
__device__ __forceinline__ uint32_t swz(int row, int c) {
    return (uint32_t)(row * 128 + ((c ^ (row & 7)) << 4));
}

// -------------------- prep kernels --------------------------------------------
__global__ __launch_bounds__(256) void bias_combine_kernel(
    const float* __restrict__ Wp, const float* __restrict__ bv,
    const float* __restrict__ bp)
{
    int row = blockIdx.x * 8 + (threadIdx.x >> 5);
    int lane = threadIdx.x & 31;
    float s = 0.f;
    for (int j = lane * 4; j < KDIM; j += 128) {
        float4 w = *(const float4*)(Wp + (size_t)row * KDIM + j);
        float4 b = *(const float4*)(bv + j);
        s += w.x * b.x + w.y * b.y + w.z * b.z + w.w * b.w;
    }
#pragma unroll
    for (int o = 16; o > 0; o >>= 1) s += __shfl_xor_sync(0xffffffff, s, o);
    if (lane == 0) g_bcomb[row] = 2048.0f * s + bp[row];
}

// compact split: src [rows,1024] fp32 -> hi/lo [rows,1024] bf16 (same layout)
__global__ __launch_bounds__(256) void split_compact_kernel(
    const float* __restrict__ src, __nv_bfloat16* __restrict__ hi,
    __nv_bfloat16* __restrict__ lo, int total4)
{
    int idx = blockIdx.x * blockDim.x + threadIdx.x;
    if (idx >= total4) return;
    float4 v = *(const float4*)(src + (size_t)idx * 4);
    __nv_bfloat16 h[4], l[4];
    split2(v.x, h[0], l[0]);
    split2(v.y, h[1], l[1]);
    split2(v.z, h[2], l[2]);
    split2(v.w, h[3], l[3]);
    __nv_bfloat162 hh0; hh0.x = h[0]; hh0.y = h[1];
    __nv_bfloat162 hh1; hh1.x = h[2]; hh1.y = h[3];
    __nv_bfloat162 ll0; ll0.x = l[0]; ll0.y = l[1];
    __nv_bfloat162 ll1; ll1.x = l[2]; ll1.y = l[3];
    *(__nv_bfloat162*)(hi + (size_t)idx * 4) = hh0;
    *(__nv_bfloat162*)(hi + (size_t)idx * 4 + 2) = hh1;
    *(__nv_bfloat162*)(lo + (size_t)idx * 4) = ll0;
    *(__nv_bfloat162*)(lo + (size_t)idx * 4 + 2) = ll1;
}

// Wv [K,N] -> Wv^T splits [N,K]
__global__ __launch_bounds__(256) void wv_transpose_split_kernel(
    const float* __restrict__ Wv, __nv_bfloat16* __restrict__ dhi,
    __nv_bfloat16* __restrict__ dlo)
{
    __shared__ float t[32][33];
    int bx = blockIdx.x * 32;
    int by = blockIdx.y * 32;
    int tx = threadIdx.x & 31, ty = threadIdx.x >> 5;
#pragma unroll
    for (int i = 0; i < 32; i += 8)
        t[ty + i][tx] = Wv[(size_t)(by + ty + i) * KDIM + bx + tx];
    __syncthreads();
#pragma unroll
    for (int i = 0; i < 32; i += 8) {
        float v = t[tx][ty + i];
        __nv_bfloat16 hi, lo;
        split2(v, hi, lo);
        size_t o = (size_t)(bx + ty + i) * KDIM + by + tx;
        dhi[o] = hi;
        dlo[o] = lo;
    }
}

// -------------------- HMMA NT GEMM, 3-product split ---------------------------
// C = (Ahi+Alo)(Bhi+Blo)^T approx = Ahi Bhi^T + Ahi Blo^T + Alo Bhi^T
// A* [M,1024] rm, B* [N,1024] rm, fp32 acc.
// MODE 0: epilogue -> split into (Chi, Clo) compact arrays [M,1024].
// MODE 1: epilogue -> 2048*acc + g_bcomb[n] into Cout.
template <int MODE>
__global__ __launch_bounds__(256, 1) void hmma_gemm_kernel(
    const __nv_bfloat16* __restrict__ Ahi, const __nv_bfloat16* __restrict__ Alo,
    const __nv_bfloat16* __restrict__ Bhi, const __nv_bfloat16* __restrict__ Blo,
    float* __restrict__ Cout, __nv_bfloat16* __restrict__ Chi,
    __nv_bfloat16* __restrict__ Clo)
{
    extern __shared__ char smem[];
    const uint32_t sbase = sptr(smem);

    const int tid = threadIdx.x;
    const int wid = tid >> 5, lane = tid & 31;
    const int wm = wid & 3, wn = wid >> 2;
    const int bm = blockIdx.y * BM, bn = blockIdx.x * BN;

    float acc[2][8][4];
#pragma unroll
    for (int i = 0; i < 2; i++)
#pragma unroll
        for (int j = 0; j < 8; j++)
#pragma unroll
            for (int q = 0; q < 4; q++) acc[i][j][q] = 0.f;

    // stage layout: [Ahi 16K | Alo 16K | Bhi 16K | Blo 16K]
    auto load_stage = [&](int t, int s) {
        uint32_t st = sbase + s * STAGE_BYTES;
        int kcol = t * BK;
#pragma unroll
        for (int i = 0; i < 4; i++) {
            int chunk = tid + i * 256;          // 0..1023
            int r = chunk >> 3, c = chunk & 7;
            uint32_t sw = swz(r, c);
            size_t aoff = (size_t)(bm + r) * KDIM + kcol + c * 8;
            size_t boff = (size_t)(bn + r) * KDIM + kcol + c * 8;
            cp_async16(st + sw, Ahi + aoff);
            cp_async16(st + 16384 + sw, Alo + aoff);
            cp_async16(st + 32768 + sw, Bhi + boff);
            cp_async16(st + 49152 + sw, Blo + boff);
        }
    };

    const int NT = KDIM / BK;  // 16
#pragma unroll
    for (int t = 0; t < STAGES - 1; t++) { load_stage(t, t); cp_commit(); }

    const int lrow = (lane & 7) + ((lane >> 3) & 1) * 8;
    const int lcol = lane >> 4;

    for (int kt = 0; kt < NT; kt++) {
        cp_wait<STAGES - 2>();
        __syncthreads();
        if (kt + STAGES - 1 < NT)
            load_stage(kt + STAGES - 1, (kt + STAGES - 1) % STAGES);
        cp_commit();

        uint32_t sah = sbase + (kt % STAGES) * STAGE_BYTES;
        uint32_t sal = sah + 16384, sbh = sah + 32768, sbl = sah + 49152;

#pragma unroll
        for (int s = 0; s < BK / 16; s++) {
            uint32_t ah[2][4], al[2][4], bh[4][4], bl[4][4];
#pragma unroll
            for (int im = 0; im < 2; im++) {
                uint32_t o = swz(wm * 32 + im * 16 + lrow, s * 2 + lcol);
                ldmatrix4(ah[im], sah + o);
                ldmatrix4(al[im], sal + o);
            }
#pragma unroll
            for (int jn = 0; jn < 4; jn++) {
                uint32_t o = swz(wn * 64 + jn * 16 + lrow, s * 2 + lcol);
                ldmatrix4(bh[jn], sbh + o);
                ldmatrix4(bl[jn], sbl + o);
            }
            // three products, fragments reused
#pragma unroll
            for (int im = 0; im < 2; im++)
#pragma unroll
                for (int n8 = 0; n8 < 8; n8++) {
                    int jn = n8 >> 1, h = n8 & 1;
                    mma16816(acc[im][n8], ah[im], bh[jn][h], bh[jn][h + 2]);
                    mma16816(acc[im][n8], ah[im], bl[jn][h], bl[jn][h + 2]);
                    mma16816(acc[im][n8], al[im], bh[jn][h], bh[jn][h + 2]);
                }
        }
    }

    // epilogue (registers -> gmem)
    const int qr = lane >> 2, qc = lane & 3;
#pragma unroll
    for (int im = 0; im < 2; im++) {
        int m0 = bm + wm * 32 + im * 16 + qr;
#pragma unroll
        for (int n8 = 0; n8 < 8; n8++) {
            int n0 = bn + wn * 64 + n8 * 8 + qc * 2;
            float* c = acc[im][n8];
            if (MODE == 1) {
                float b0 = g_bcomb[n0], b1 = g_bcomb[n0 + 1];
                *(float2*)(Cout + (size_t)m0 * NMAIN + n0) =
                    make_float2(2048.f * c[0] + b0, 2048.f * c[1] + b1);
                *(float2*)(Cout + (size_t)(m0 + 8) * NMAIN + n0) =
                    make_float2(2048.f * c[2] + b0, 2048.f * c[3] + b1);
            } else {
#pragma unroll
                for (int q = 0; q < 4; q++) {
                    int m = m0 + (q >> 1) * 8;
                    int n = n0 + (q & 1);
                    __nv_bfloat16 hi, lo;
                    split2(c[q], hi, lo);
                    size_t o = (size_t)m * KDIM + n;
                    Chi[o] = hi;
                    Clo[o] = lo;
                }
            }
        }
    }
}

// -------------------- host ------------------------------------------------------
extern "C" void kernel_launch(void* const* d_in, const int* in_sizes, int n_in,
                              void* d_out, int out_size)
{
    // metadata order: x, Wq, bq, Wk, bk, Wv, bv, Wp, bp
    const float* x  = (const float*)d_in[0];
    const float* Wv = (const float*)d_in[5];
    const float* bv = (const float*)d_in[6];
    const float* Wp = (const float*)d_in[7];
    const float* bp = (const float*)d_in[8];
    float* out = (float*)d_out;

    __nv_bfloat16 *xhi, *xlo, *wphi, *wplo, *wvthi, *wvtlo, *wchi, *wclo;
    cudaGetSymbolAddress((void**)&xhi, g_xhi);
    cudaGetSymbolAddress((void**)&xlo, g_xlo);
    cudaGetSymbolAddress((void**)&wphi, g_wphi);
    cudaGetSymbolAddress((void**)&wplo, g_wplo);
    cudaGetSymbolAddress((void**)&wvthi, g_wvthi);
    cudaGetSymbolAddress((void**)&wvtlo, g_wvtlo);
    cudaGetSymbolAddress((void**)&wchi, g_wchi);
    cudaGetSymbolAddress((void**)&wclo, g_wclo);

    cudaFuncSetAttribute(hmma_gemm_kernel<0>,
                         cudaFuncAttributeMaxDynamicSharedMemorySize, SMEM_TOTAL);
    cudaFuncSetAttribute(hmma_gemm_kernel<1>,
                         cudaFuncAttributeMaxDynamicSharedMemorySize, SMEM_TOTAL);

    bias_combine_kernel<<<128, 256>>>(Wp, bv, bp);
    split_compact_kernel<<<(MMAIN * KDIM / 4 + 255) / 256, 256>>>(x, xhi, xlo,
                                                                  MMAIN * KDIM / 4);
    split_compact_kernel<<<(KDIM * KDIM / 4 + 255) / 256, 256>>>(Wp, wphi, wplo,
                                                                 KDIM * KDIM / 4);
    wv_transpose_split_kernel<<<dim3(32, 32), 256>>>(Wv, wvthi, wvtlo);

    // Wc = Wp @ Wv  -> compact split (wchi, wclo)
    hmma_gemm_kernel<0><<<dim3(8, 8), 256, SMEM_TOTAL>>>(
        wphi, wplo, wvthi, wvtlo, nullptr, wchi, wclo);
    // out = 2048 * x @ Wc^T + bcomb
    hmma_gemm_kernel<1><<<dim3(8, 64), 256, SMEM_TOTAL>>>(
        xhi, xlo, wchi, wclo, out, nullptr, nullptr);
}

// round 6
// speedup vs baseline: 3.8867x; 1.7696x over previous
#include <cuda_runtime.h>
#include <cuda_fp16.h>
#include <cstdint>

// ============================================================================
// Collapse (verified): out = 2048 * x @ (Wp@Wv)^T + (2048*Wp@bv + bp)
// Legacy HMMA mma.sync (tcgen05 rejected at base-sm_103 PTX target).
//
// R6: fp16 instead of bf16. fp16 rounding = 2^-11 -> expected global-L2
// rel_err ~ 4e-4 < 1e-3 gate. Main GEMM becomes SINGLE-product fp16
// (3x fewer MMAs than R5). Wc = Wp@Wv stays 3-product fp16 split so Wc is
// accurate to one fp16 rounding.
// ============================================================================

#define KDIM 1024
#define MMAIN 8192
#define NMAIN 1024

#define BM 128
#define BN 128
#define BK 64

// ---- wc gemm (3-product): stage = Ahi|Alo|Bhi|Blo = 64KB, 3 stages
#define WSTAGES 3
#define WSTAGE_BYTES 65536
#define WSMEM_TOTAL (WSTAGES * WSTAGE_BYTES)
// ---- main gemm (1-product): stage = A|B = 32KB, 4 stages
#define MSTAGES 4
#define MSTAGE_BYTES 32768
#define MSMEM_TOTAL (MSTAGES * MSTAGE_BYTES)

// -------------------- scratch (device globals) -------------------------------
__device__ __half g_xh[(size_t)MMAIN * KDIM];    // fp16(x)
__device__ __half g_wph[(size_t)KDIM * KDIM];    // fp16 hi(Wp)
__device__ __half g_wpl[(size_t)KDIM * KDIM];    // fp16 lo(Wp)
__device__ __half g_wvth[(size_t)KDIM * KDIM];   // fp16 hi(Wv^T)
__device__ __half g_wvtl[(size_t)KDIM * KDIM];   // fp16 lo(Wv^T)
__device__ __half g_wch[(size_t)KDIM * KDIM];    // fp16(Wc)
__device__ float g_bcomb[KDIM];

// -------------------- helpers -------------------------------------------------
__device__ __forceinline__ uint32_t sptr(const void* p) {
    return (uint32_t)__cvta_generic_to_shared(p);
}
__device__ __forceinline__ void cp_async16(uint32_t smem, const void* gmem) {
    asm volatile("cp.async.cg.shared.global [%0], [%1], 16;"
                 :: "r"(smem), "l"(gmem) : "memory");
}
__device__ __forceinline__ void cp_commit() {
    asm volatile("cp.async.commit_group;" ::: "memory");
}
template <int N> __device__ __forceinline__ void cp_wait() {
    asm volatile("cp.async.wait_group %0;" :: "n"(N) : "memory");
}
__device__ __forceinline__ void ldmatrix4(uint32_t* r, uint32_t addr) {
    asm volatile("ldmatrix.sync.aligned.m8n8.x4.shared.b16 {%0,%1,%2,%3}, [%4];"
                 : "=r"(r[0]), "=r"(r[1]), "=r"(r[2]), "=r"(r[3]) : "r"(addr));
}
__device__ __forceinline__ void mma16816(float* c, const uint32_t* a,
                                         uint32_t b0, uint32_t b1) {
    asm volatile(
        "mma.sync.aligned.m16n8k16.row.col.f32.f16.f16.f32 "
        "{%0,%1,%2,%3}, {%4,%5,%6,%7}, {%8,%9}, {%0,%1,%2,%3};"
        : "+f"(c[0]), "+f"(c[1]), "+f"(c[2]), "+f"(c[3])
        : "r"(a[0]), "r"(a[1]), "r"(a[2]), "r"(a[3]), "r"(b0), "r"(b1));
}
__device__ __forceinline__ void split2h(float v, __half& hi, __half& lo) {
    hi = __float2half_rn(v);
    lo = __float2half_rn(v - __half2float(hi));
}
__device__ __forceinline__ uint32_t swz(int row, int c) {
    return (uint32_t)(row * 128 + ((c ^ (row & 7)) << 4));
}

// -------------------- prep kernels --------------------------------------------
__global__ __launch_bounds__(256) void bias_combine_kernel(
    const float* __restrict__ Wp, const float* __restrict__ bv,
    const float* __restrict__ bp)
{
    int row = blockIdx.x * 8 + (threadIdx.x >> 5);
    int lane = threadIdx.x & 31;
    float s = 0.f;
    for (int j = lane * 4; j < KDIM; j += 128) {
        float4 w = *(const float4*)(Wp + (size_t)row * KDIM + j);
        float4 b = *(const float4*)(bv + j);
        s += w.x * b.x + w.y * b.y + w.z * b.z + w.w * b.w;
    }
#pragma unroll
    for (int o = 16; o > 0; o >>= 1) s += __shfl_xor_sync(0xffffffff, s, o);
    if (lane == 0) g_bcomb[row] = 2048.0f * s + bp[row];
}

// x fp32 -> fp16, 4 elems/thread
__global__ __launch_bounds__(256) void convert_x_kernel(
    const float* __restrict__ src, __half* __restrict__ dst, int total4)
{
    int idx = blockIdx.x * blockDim.x + threadIdx.x;
    if (idx >= total4) return;
    float4 v = *(const float4*)(src + (size_t)idx * 4);
    __half2 h0 = __floats2half2_rn(v.x, v.y);
    __half2 h1 = __floats2half2_rn(v.z, v.w);
    *(__half2*)(dst + (size_t)idx * 4) = h0;
    *(__half2*)(dst + (size_t)idx * 4 + 2) = h1;
}

// Wp fp32 -> fp16 hi/lo (same layout)
__global__ __launch_bounds__(256) void split_compact_kernel(
    const float* __restrict__ src, __half* __restrict__ hi,
    __half* __restrict__ lo, int total4)
{
    int idx = blockIdx.x * blockDim.x + threadIdx.x;
    if (idx >= total4) return;
    float4 v = *(const float4*)(src + (size_t)idx * 4);
    __half h[4], l[4];
    split2h(v.x, h[0], l[0]);
    split2h(v.y, h[1], l[1]);
    split2h(v.z, h[2], l[2]);
    split2h(v.w, h[3], l[3]);
    __half2 hh0; hh0.x = h[0]; hh0.y = h[1];
    __half2 hh1; hh1.x = h[2]; hh1.y = h[3];
    __half2 ll0; ll0.x = l[0]; ll0.y = l[1];
    __half2 ll1; ll1.x = l[2]; ll1.y = l[3];
    *(__half2*)(hi + (size_t)idx * 4) = hh0;
    *(__half2*)(hi + (size_t)idx * 4 + 2) = hh1;
    *(__half2*)(lo + (size_t)idx * 4) = ll0;
    *(__half2*)(lo + (size_t)idx * 4 + 2) = ll1;
}

// Wv [K,N] -> Wv^T fp16 hi/lo [N,K]
__global__ __launch_bounds__(256) void wv_transpose_split_kernel(
    const float* __restrict__ Wv, __half* __restrict__ dhi,
    __half* __restrict__ dlo)
{
    __shared__ float t[32][33];
    int bx = blockIdx.x * 32;
    int by = blockIdx.y * 32;
    int tx = threadIdx.x & 31, ty = threadIdx.x >> 5;
#pragma unroll
    for (int i = 0; i < 32; i += 8)
        t[ty + i][tx] = Wv[(size_t)(by + ty + i) * KDIM + bx + tx];
    __syncthreads();
#pragma unroll
    for (int i = 0; i < 32; i += 8) {
        float v = t[tx][ty + i];
        __half hi, lo;
        split2h(v, hi, lo);
        size_t o = (size_t)(bx + ty + i) * KDIM + by + tx;
        dhi[o] = hi;
        dlo[o] = lo;
    }
}

// -------------------- wc GEMM: 3-product fp16 split ---------------------------
// Wc = Wp @ Wv; A=(wph,wpl) [1024,1024], B=(wvth,wvtl) [1024,1024] (NT).
// Epilogue: g_wch = fp16(acc).
__global__ __launch_bounds__(256, 1) void wc_gemm_kernel(
    const __half* __restrict__ Ahi, const __half* __restrict__ Alo,
    const __half* __restrict__ Bhi, const __half* __restrict__ Blo,
    __half* __restrict__ Ch)
{
    extern __shared__ char smem[];
    const uint32_t sbase = sptr(smem);
    const int tid = threadIdx.x;
    const int wid = tid >> 5, lane = tid & 31;
    const int wm = wid & 3, wn = wid >> 2;
    const int bm = blockIdx.y * BM, bn = blockIdx.x * BN;

    float acc[2][8][4];
#pragma unroll
    for (int i = 0; i < 2; i++)
#pragma unroll
        for (int j = 0; j < 8; j++)
#pragma unroll
            for (int q = 0; q < 4; q++) acc[i][j][q] = 0.f;

    auto load_stage = [&](int t, int s) {
        uint32_t st = sbase + s * WSTAGE_BYTES;
        int kcol = t * BK;
#pragma unroll
        for (int i = 0; i < 4; i++) {
            int chunk = tid + i * 256;
            int r = chunk >> 3, c = chunk & 7;
            uint32_t sw = swz(r, c);
            size_t aoff = (size_t)(bm + r) * KDIM + kcol + c * 8;
            size_t boff = (size_t)(bn + r) * KDIM + kcol + c * 8;
            cp_async16(st + sw, Ahi + aoff);
            cp_async16(st + 16384 + sw, Alo + aoff);
            cp_async16(st + 32768 + sw, Bhi + boff);
            cp_async16(st + 49152 + sw, Blo + boff);
        }
    };

    const int NT = KDIM / BK;  // 16
#pragma unroll
    for (int t = 0; t < WSTAGES - 1; t++) { load_stage(t, t); cp_commit(); }

    const int lrow = (lane & 7) + ((lane >> 3) & 1) * 8;
    const int lcol = lane >> 4;

    for (int kt = 0; kt < NT; kt++) {
        cp_wait<WSTAGES - 2>();
        __syncthreads();
        if (kt + WSTAGES - 1 < NT)
            load_stage(kt + WSTAGES - 1, (kt + WSTAGES - 1) % WSTAGES);
        cp_commit();

        uint32_t sah = sbase + (kt % WSTAGES) * WSTAGE_BYTES;
        uint32_t sal = sah + 16384, sbh = sah + 32768, sbl = sah + 49152;

#pragma unroll
        for (int s = 0; s < BK / 16; s++) {
            uint32_t ah[2][4], al[2][4], bh[4][4], bl[4][4];
#pragma unroll
            for (int im = 0; im < 2; im++) {
                uint32_t o = swz(wm * 32 + im * 16 + lrow, s * 2 + lcol);
                ldmatrix4(ah[im], sah + o);
                ldmatrix4(al[im], sal + o);
            }
#pragma unroll
            for (int jn = 0; jn < 4; jn++) {
                uint32_t o = swz(wn * 64 + jn * 16 + lrow, s * 2 + lcol);
                ldmatrix4(bh[jn], sbh + o);
                ldmatrix4(bl[jn], sbl + o);
            }
#pragma unroll
            for (int im = 0; im < 2; im++)
#pragma unroll
                for (int n8 = 0; n8 < 8; n8++) {
                    int jn = n8 >> 1, h = n8 & 1;
                    mma16816(acc[im][n8], ah[im], bh[jn][h], bh[jn][h + 2]);
                    mma16816(acc[im][n8], ah[im], bl[jn][h], bl[jn][h + 2]);
                    mma16816(acc[im][n8], al[im], bh[jn][h], bh[jn][h + 2]);
                }
        }
    }

    const int qr = lane >> 2, qc = lane & 3;
#pragma unroll
    for (int im = 0; im < 2; im++) {
        int m0 = bm + wm * 32 + im * 16 + qr;
#pragma unroll
        for (int n8 = 0; n8 < 8; n8++) {
            int n0 = bn + wn * 64 + n8 * 8 + qc * 2;
            float* c = acc[im][n8];
#pragma unroll
            for (int q = 0; q < 4; q++) {
                int m = m0 + (q >> 1) * 8;
                int n = n0 + (q & 1);
                Ch[(size_t)m * KDIM + n] = __float2half_rn(c[q]);
            }
        }
    }
}

// -------------------- main GEMM: single-product fp16 --------------------------
// out = 2048 * Xh @ Wch^T + bcomb ; Xh [8192,1024], Wch [1024,1024] (NT).
__global__ __launch_bounds__(256, 1) void main_gemm_kernel(
    const __half* __restrict__ A, const __half* __restrict__ B,
    float* __restrict__ Cout)
{
    extern __shared__ char smem[];
    const uint32_t sbase = sptr(smem);
    const int tid = threadIdx.x;
    const int wid = tid >> 5, lane = tid & 31;
    const int wm = wid & 3, wn = wid >> 2;
    const int bm = blockIdx.y * BM, bn = blockIdx.x * BN;

    float acc[2][8][4];
#pragma unroll
    for (int i = 0; i < 2; i++)
#pragma unroll
        for (int j = 0; j < 8; j++)
#pragma unroll
            for (int q = 0; q < 4; q++) acc[i][j][q] = 0.f;

    auto load_stage = [&](int t, int s) {
        uint32_t sa = sbase + s * MSTAGE_BYTES;
        uint32_t sb = sa + 16384;
        int kcol = t * BK;
#pragma unroll
        for (int i = 0; i < 4; i++) {
            int chunk = tid + i * 256;
            int r = chunk >> 3, c = chunk & 7;
            uint32_t sw = swz(r, c);
            cp_async16(sa + sw, A + (size_t)(bm + r) * KDIM + kcol + c * 8);
            cp_async16(sb + sw, B + (size_t)(bn + r) * KDIM + kcol + c * 8);
        }
    };

    const int NT = KDIM / BK;  // 16
#pragma unroll
    for (int t = 0; t < MSTAGES - 1; t++) { load_stage(t, t); cp_commit(); }

    const int lrow = (lane & 7) + ((lane >> 3) & 1) * 8;
    const int lcol = lane >> 4;

    for (int kt = 0; kt < NT; kt++) {
        cp_wait<MSTAGES - 2>();
        __syncthreads();
        if (kt + MSTAGES - 1 < NT)
            load_stage(kt + MSTAGES - 1, (kt + MSTAGES - 1) % MSTAGES);
        cp_commit();

        uint32_t sa = sbase + (kt % MSTAGES) * MSTAGE_BYTES;
        uint32_t sb = sa + 16384;

#pragma unroll
        for (int s = 0; s < BK / 16; s++) {
            uint32_t af[2][4], bf[4][4];
#pragma unroll
            for (int im = 0; im < 2; im++)
                ldmatrix4(af[im], sa + swz(wm * 32 + im * 16 + lrow,
                                           s * 2 + lcol));
#pragma unroll
            for (int jn = 0; jn < 4; jn++)
                ldmatrix4(bf[jn], sb + swz(wn * 64 + jn * 16 + lrow,
                                           s * 2 + lcol));
#pragma unroll
            for (int im = 0; im < 2; im++)
#pragma unroll
                for (int n8 = 0; n8 < 8; n8++) {
                    int jn = n8 >> 1, h = n8 & 1;
                    mma16816(acc[im][n8], af[im], bf[jn][h], bf[jn][h + 2]);
                }
        }
    }

    const int qr = lane >> 2, qc = lane & 3;
#pragma unroll
    for (int im = 0; im < 2; im++) {
        int m0 = bm + wm * 32 + im * 16 + qr;
#pragma unroll
        for (int n8 = 0; n8 < 8; n8++) {
            int n0 = bn + wn * 64 + n8 * 8 + qc * 2;
            float* c = acc[im][n8];
            float b0 = g_bcomb[n0], b1 = g_bcomb[n0 + 1];
            *(float2*)(Cout + (size_t)m0 * NMAIN + n0) =
                make_float2(2048.f * c[0] + b0, 2048.f * c[1] + b1);
            *(float2*)(Cout + (size_t)(m0 + 8) * NMAIN + n0) =
                make_float2(2048.f * c[2] + b0, 2048.f * c[3] + b1);
        }
    }
}

// -------------------- host ------------------------------------------------------
extern "C" void kernel_launch(void* const* d_in, const int* in_sizes, int n_in,
                              void* d_out, int out_size)
{
    // metadata order: x, Wq, bq, Wk, bk, Wv, bv, Wp, bp
    const float* x  = (const float*)d_in[0];
    const float* Wv = (const float*)d_in[5];
    const float* bv = (const float*)d_in[6];
    const float* Wp = (const float*)d_in[7];
    const float* bp = (const float*)d_in[8];
    float* out = (float*)d_out;

    __half *xh, *wph, *wpl, *wvth, *wvtl, *wch;
    cudaGetSymbolAddress((void**)&xh, g_xh);
    cudaGetSymbolAddress((void**)&wph, g_wph);
    cudaGetSymbolAddress((void**)&wpl, g_wpl);
    cudaGetSymbolAddress((void**)&wvth, g_wvth);
    cudaGetSymbolAddress((void**)&wvtl, g_wvtl);
    cudaGetSymbolAddress((void**)&wch, g_wch);

    cudaFuncSetAttribute(wc_gemm_kernel,
                         cudaFuncAttributeMaxDynamicSharedMemorySize, WSMEM_TOTAL);
    cudaFuncSetAttribute(main_gemm_kernel,
                         cudaFuncAttributeMaxDynamicSharedMemorySize, MSMEM_TOTAL);

    bias_combine_kernel<<<128, 256>>>(Wp, bv, bp);
    convert_x_kernel<<<(MMAIN * KDIM / 4 + 255) / 256, 256>>>(x, xh,
                                                              MMAIN * KDIM / 4);
    split_compact_kernel<<<(KDIM * KDIM / 4 + 255) / 256, 256>>>(Wp, wph, wpl,
                                                                 KDIM * KDIM / 4);
    wv_transpose_split_kernel<<<dim3(32, 32), 256>>>(Wv, wvth, wvtl);

    wc_gemm_kernel<<<dim3(8, 8), 256, WSMEM_TOTAL>>>(wph, wpl, wvth, wvtl, wch);
    main_gemm_kernel<<<dim3(8, 64), 256, MSMEM_TOTAL>>>(xh, wch, out);
}

// round 7
// speedup vs baseline: 4.9520x; 1.2741x over previous
#include <cuda_runtime.h>
#include <cuda_fp16.h>
#include <cstdint>

// ============================================================================
// Collapse (verified): out = 2048 * x @ (Wp@Wv)^T + (2048*Wp@bv + bp)
// fp16 HMMA path (R6, rel_err 2.9e-4).
// R7: occupancy work. main GEMM: 3 stages (96KB) + launch_bounds(256,2)
//     -> 2 CTAs/SM, 1.73 waves (was 1 CTA/SM, 3.46 waves).
//     wc GEMM: 64x128 tiles -> 128 CTAs (was 64 on 148 SMs).
// ============================================================================

#define KDIM 1024
#define MMAIN 8192
#define NMAIN 1024
#define BK 64

// ---- wc gemm: BM=64, BN=128, 3-product; stage = Ahi|Alo 16K + Bhi|Blo 32K
#define WBM 64
#define WBN 128
#define WSTAGES 3
#define WSTAGE_BYTES 49152
#define WSMEM_TOTAL (WSTAGES * WSTAGE_BYTES)   // 144 KB
// ---- main gemm: BM=BN=128, 1-product; stage = A|B = 32KB, 3 stages
#define MBM 128
#define MBN 128
#define MSTAGES 3
#define MSTAGE_BYTES 32768
#define MSMEM_TOTAL (MSTAGES * MSTAGE_BYTES)   // 96 KB -> 2 CTAs/SM

// -------------------- scratch -------------------------------------------------
__device__ __half g_xh[(size_t)MMAIN * KDIM];
__device__ __half g_wph[(size_t)KDIM * KDIM];
__device__ __half g_wpl[(size_t)KDIM * KDIM];
__device__ __half g_wvth[(size_t)KDIM * KDIM];
__device__ __half g_wvtl[(size_t)KDIM * KDIM];
__device__ __half g_wch[(size_t)KDIM * KDIM];
__device__ float g_bcomb[KDIM];

// -------------------- helpers -------------------------------------------------
__device__ __forceinline__ uint32_t sptr(const void* p) {
    return (uint32_t)__cvta_generic_to_shared(p);
}
__device__ __forceinline__ void cp_async16(uint32_t smem, const void* gmem) {
    asm volatile("cp.async.cg.shared.global [%0], [%1], 16;"
                 :: "r"(smem), "l"(gmem) : "memory");
}
__device__ __forceinline__ void cp_commit() {
    asm volatile("cp.async.commit_group;" ::: "memory");
}
template <int N> __device__ __forceinline__ void cp_wait() {
    asm volatile("cp.async.wait_group %0;" :: "n"(N) : "memory");
}
__device__ __forceinline__ void ldmatrix4(uint32_t* r, uint32_t addr) {
    asm volatile("ldmatrix.sync.aligned.m8n8.x4.shared.b16 {%0,%1,%2,%3}, [%4];"
                 : "=r"(r[0]), "=r"(r[1]), "=r"(r[2]), "=r"(r[3]) : "r"(addr));
}
__device__ __forceinline__ void mma16816(float* c, const uint32_t* a,
                                         uint32_t b0, uint32_t b1) {
    asm volatile(
        "mma.sync.aligned.m16n8k16.row.col.f32.f16.f16.f32 "
        "{%0,%1,%2,%3}, {%4,%5,%6,%7}, {%8,%9}, {%0,%1,%2,%3};"
        : "+f"(c[0]), "+f"(c[1]), "+f"(c[2]), "+f"(c[3])
        : "r"(a[0]), "r"(a[1]), "r"(a[2]), "r"(a[3]), "r"(b0), "r"(b1));
}
__device__ __forceinline__ void split2h(float v, __half& hi, __half& lo) {
    hi = __float2half_rn(v);
    lo = __float2half_rn(v - __half2float(hi));
}
__device__ __forceinline__ uint32_t swz(int row, int c) {
    return (uint32_t)(row * 128 + ((c ^ (row & 7)) << 4));
}

// -------------------- prep kernels --------------------------------------------
__global__ __launch_bounds__(256) void bias_combine_kernel(
    const float* __restrict__ Wp, const float* __restrict__ bv,
    const float* __restrict__ bp)
{
    int row = blockIdx.x * 8 + (threadIdx.x >> 5);
    int lane = threadIdx.x & 31;
    float s = 0.f;
    for (int j = lane * 4; j < KDIM; j += 128) {
        float4 w = *(const float4*)(Wp + (size_t)row * KDIM + j);
        float4 b = *(const float4*)(bv + j);
        s += w.x * b.x + w.y * b.y + w.z * b.z + w.w * b.w;
    }
#pragma unroll
    for (int o = 16; o > 0; o >>= 1) s += __shfl_xor_sync(0xffffffff, s, o);
    if (lane == 0) g_bcomb[row] = 2048.0f * s + bp[row];
}

__global__ __launch_bounds__(256) void convert_x_kernel(
    const float* __restrict__ src, __half* __restrict__ dst, int total4)
{
    int idx = blockIdx.x * blockDim.x + threadIdx.x;
    if (idx >= total4) return;
    float4 v = *(const float4*)(src + (size_t)idx * 4);
    *(__half2*)(dst + (size_t)idx * 4) = __floats2half2_rn(v.x, v.y);
    *(__half2*)(dst + (size_t)idx * 4 + 2) = __floats2half2_rn(v.z, v.w);
}

__global__ __launch_bounds__(256) void split_compact_kernel(
    const float* __restrict__ src, __half* __restrict__ hi,
    __half* __restrict__ lo, int total4)
{
    int idx = blockIdx.x * blockDim.x + threadIdx.x;
    if (idx >= total4) return;
    float4 v = *(const float4*)(src + (size_t)idx * 4);
    __half h[4], l[4];
    split2h(v.x, h[0], l[0]);
    split2h(v.y, h[1], l[1]);
    split2h(v.z, h[2], l[2]);
    split2h(v.w, h[3], l[3]);
    __half2 hh0; hh0.x = h[0]; hh0.y = h[1];
    __half2 hh1; hh1.x = h[2]; hh1.y = h[3];
    __half2 ll0; ll0.x = l[0]; ll0.y = l[1];
    __half2 ll1; ll1.x = l[2]; ll1.y = l[3];
    *(__half2*)(hi + (size_t)idx * 4) = hh0;
    *(__half2*)(hi + (size_t)idx * 4 + 2) = hh1;
    *(__half2*)(lo + (size_t)idx * 4) = ll0;
    *(__half2*)(lo + (size_t)idx * 4 + 2) = ll1;
}

__global__ __launch_bounds__(256) void wv_transpose_split_kernel(
    const float* __restrict__ Wv, __half* __restrict__ dhi,
    __half* __restrict__ dlo)
{
    __shared__ float t[32][33];
    int bx = blockIdx.x * 32;
    int by = blockIdx.y * 32;
    int tx = threadIdx.x & 31, ty = threadIdx.x >> 5;
#pragma unroll
    for (int i = 0; i < 32; i += 8)
        t[ty + i][tx] = Wv[(size_t)(by + ty + i) * KDIM + bx + tx];
    __syncthreads();
#pragma unroll
    for (int i = 0; i < 32; i += 8) {
        float v = t[tx][ty + i];
        __half hi, lo;
        split2h(v, hi, lo);
        size_t o = (size_t)(bx + ty + i) * KDIM + by + tx;
        dhi[o] = hi;
        dlo[o] = lo;
    }
}

// -------------------- wc GEMM: 64x128 tiles, 3-product fp16 split -------------
// Wc = Wp @ Wv (NT). 8 warps: wm = wid&1 (32-row strip), wn = wid>>1 (32-col).
// grid (WBN tiles=8, WBM tiles=16) = 128 CTAs.
__global__ __launch_bounds__(256, 1) void wc_gemm_kernel(
    const __half* __restrict__ Ahi, const __half* __restrict__ Alo,
    const __half* __restrict__ Bhi, const __half* __restrict__ Blo,
    __half* __restrict__ Ch)
{
    extern __shared__ char smem[];
    const uint32_t sbase = sptr(smem);
    const int tid = threadIdx.x;
    const int wid = tid >> 5, lane = tid & 31;
    const int wm = wid & 1, wn = wid >> 1;
    const int bm = blockIdx.y * WBM, bn = blockIdx.x * WBN;

    float acc[2][4][4];
#pragma unroll
    for (int i = 0; i < 2; i++)
#pragma unroll
        for (int j = 0; j < 4; j++)
#pragma unroll
            for (int q = 0; q < 4; q++) acc[i][j][q] = 0.f;

    // stage: [Ahi 8K | Alo 8K | Bhi 16K | Blo 16K]
    auto load_stage = [&](int t, int s) {
        uint32_t st = sbase + s * WSTAGE_BYTES;
        int kcol = t * BK;
        // A: 64 rows x 8 chunks = 512 -> 2 iters
#pragma unroll
        for (int i = 0; i < 2; i++) {
            int chunk = tid + i * 256;
            int r = chunk >> 3, c = chunk & 7;
            uint32_t sw = swz(r, c);
            size_t aoff = (size_t)(bm + r) * KDIM + kcol + c * 8;
            cp_async16(st + sw, Ahi + aoff);
            cp_async16(st + 8192 + sw, Alo + aoff);
        }
        // B: 128 rows x 8 chunks = 1024 -> 4 iters
#pragma unroll
        for (int i = 0; i < 4; i++) {
            int chunk = tid + i * 256;
            int r = chunk >> 3, c = chunk & 7;
            uint32_t sw = swz(r, c);
            size_t boff = (size_t)(bn + r) * KDIM + kcol + c * 8;
            cp_async16(st + 16384 + sw, Bhi + boff);
            cp_async16(st + 32768 + sw, Blo + boff);
        }
    };

    const int NT = KDIM / BK;  // 16
#pragma unroll
    for (int t = 0; t < WSTAGES - 1; t++) { load_stage(t, t); cp_commit(); }

    const int lrow = (lane & 7) + ((lane >> 3) & 1) * 8;
    const int lcol = lane >> 4;

    for (int kt = 0; kt < NT; kt++) {
        cp_wait<WSTAGES - 2>();
        __syncthreads();
        if (kt + WSTAGES - 1 < NT)
            load_stage(kt + WSTAGES - 1, (kt + WSTAGES - 1) % WSTAGES);
        cp_commit();

        uint32_t sah = sbase + (kt % WSTAGES) * WSTAGE_BYTES;
        uint32_t sal = sah + 8192, sbh = sah + 16384, sbl = sah + 32768;

#pragma unroll
        for (int s = 0; s < BK / 16; s++) {
            uint32_t ah[2][4], al[2][4], bh[2][4], bl[2][4];
#pragma unroll
            for (int im = 0; im < 2; im++) {
                uint32_t o = swz(wm * 32 + im * 16 + lrow, s * 2 + lcol);
                ldmatrix4(ah[im], sah + o);
                ldmatrix4(al[im], sal + o);
            }
#pragma unroll
            for (int jn = 0; jn < 2; jn++) {
                uint32_t o = swz(wn * 32 + jn * 16 + lrow, s * 2 + lcol);
                ldmatrix4(bh[jn], sbh + o);
                ldmatrix4(bl[jn], sbl + o);
            }
#pragma unroll
            for (int im = 0; im < 2; im++)
#pragma unroll
                for (int n8 = 0; n8 < 4; n8++) {
                    int jn = n8 >> 1, h = n8 & 1;
                    mma16816(acc[im][n8], ah[im], bh[jn][h], bh[jn][h + 2]);
                    mma16816(acc[im][n8], ah[im], bl[jn][h], bl[jn][h + 2]);
                    mma16816(acc[im][n8], al[im], bh[jn][h], bh[jn][h + 2]);
                }
        }
    }

    const int qr = lane >> 2, qc = lane & 3;
#pragma unroll
    for (int im = 0; im < 2; im++) {
        int m0 = bm + wm * 32 + im * 16 + qr;
#pragma unroll
        for (int n8 = 0; n8 < 4; n8++) {
            int n0 = bn + wn * 32 + n8 * 8 + qc * 2;
            float* c = acc[im][n8];
#pragma unroll
            for (int q = 0; q < 4; q++) {
                int m = m0 + (q >> 1) * 8;
                int n = n0 + (q & 1);
                Ch[(size_t)m * KDIM + n] = __float2half_rn(c[q]);
            }
        }
    }
}

// -------------------- main GEMM: single-product fp16, 2 CTAs/SM ---------------
__global__ __launch_bounds__(256, 2) void main_gemm_kernel(
    const __half* __restrict__ A, const __half* __restrict__ B,
    float* __restrict__ Cout)
{
    extern __shared__ char smem[];
    const uint32_t sbase = sptr(smem);
    const int tid = threadIdx.x;
    const int wid = tid >> 5, lane = tid & 31;
    const int wm = wid & 3, wn = wid >> 2;
    const int bm = blockIdx.y * MBM, bn = blockIdx.x * MBN;

    float acc[2][8][4];
#pragma unroll
    for (int i = 0; i < 2; i++)
#pragma unroll
        for (int j = 0; j < 8; j++)
#pragma unroll
            for (int q = 0; q < 4; q++) acc[i][j][q] = 0.f;

    auto load_stage = [&](int t, int s) {
        uint32_t sa = sbase + s * MSTAGE_BYTES;
        uint32_t sb = sa + 16384;
        int kcol = t * BK;
#pragma unroll
        for (int i = 0; i < 4; i++) {
            int chunk = tid + i * 256;
            int r = chunk >> 3, c = chunk & 7;
            uint32_t sw = swz(r, c);
            cp_async16(sa + sw, A + (size_t)(bm + r) * KDIM + kcol + c * 8);
            cp_async16(sb + sw, B + (size_t)(bn + r) * KDIM + kcol + c * 8);
        }
    };

    const int NT = KDIM / BK;  // 16
#pragma unroll
    for (int t = 0; t < MSTAGES - 1; t++) { load_stage(t, t); cp_commit(); }

    const int lrow = (lane & 7) + ((lane >> 3) & 1) * 8;
    const int lcol = lane >> 4;

    for (int kt = 0; kt < NT; kt++) {
        cp_wait<MSTAGES - 2>();
        __syncthreads();
        if (kt + MSTAGES - 1 < NT)
            load_stage(kt + MSTAGES - 1, (kt + MSTAGES - 1) % MSTAGES);
        cp_commit();

        uint32_t sa = sbase + (kt % MSTAGES) * MSTAGE_BYTES;
        uint32_t sb = sa + 16384;

#pragma unroll
        for (int s = 0; s < BK / 16; s++) {
            uint32_t af[2][4], bf[4][4];
#pragma unroll
            for (int im = 0; im < 2; im++)
                ldmatrix4(af[im], sa + swz(wm * 32 + im * 16 + lrow,
                                           s * 2 + lcol));
#pragma unroll
            for (int jn = 0; jn < 4; jn++)
                ldmatrix4(bf[jn], sb + swz(wn * 64 + jn * 16 + lrow,
                                           s * 2 + lcol));
#pragma unroll
            for (int im = 0; im < 2; im++)
#pragma unroll
                for (int n8 = 0; n8 < 8; n8++) {
                    int jn = n8 >> 1, h = n8 & 1;
                    mma16816(acc[im][n8], af[im], bf[jn][h], bf[jn][h + 2]);
                }
        }
    }

    const int qr = lane >> 2, qc = lane & 3;
#pragma unroll
    for (int im = 0; im < 2; im++) {
        int m0 = bm + wm * 32 + im * 16 + qr;
#pragma unroll
        for (int n8 = 0; n8 < 8; n8++) {
            int n0 = bn + wn * 64 + n8 * 8 + qc * 2;
            float* c = acc[im][n8];
            float b0 = g_bcomb[n0], b1 = g_bcomb[n0 + 1];
            *(float2*)(Cout + (size_t)m0 * NMAIN + n0) =
                make_float2(2048.f * c[0] + b0, 2048.f * c[1] + b1);
            *(float2*)(Cout + (size_t)(m0 + 8) * NMAIN + n0) =
                make_float2(2048.f * c[2] + b0, 2048.f * c[3] + b1);
        }
    }
}

// -------------------- host ------------------------------------------------------
extern "C" void kernel_launch(void* const* d_in, const int* in_sizes, int n_in,
                              void* d_out, int out_size)
{
    // metadata order: x, Wq, bq, Wk, bk, Wv, bv, Wp, bp
    const float* x  = (const float*)d_in[0];
    const float* Wv = (const float*)d_in[5];
    const float* bv = (const float*)d_in[6];
    const float* Wp = (const float*)d_in[7];
    const float* bp = (const float*)d_in[8];
    float* out = (float*)d_out;

    __half *xh, *wph, *wpl, *wvth, *wvtl, *wch;
    cudaGetSymbolAddress((void**)&xh, g_xh);
    cudaGetSymbolAddress((void**)&wph, g_wph);
    cudaGetSymbolAddress((void**)&wpl, g_wpl);
    cudaGetSymbolAddress((void**)&wvth, g_wvth);
    cudaGetSymbolAddress((void**)&wvtl, g_wvtl);
    cudaGetSymbolAddress((void**)&wch, g_wch);

    cudaFuncSetAttribute(wc_gemm_kernel,
                         cudaFuncAttributeMaxDynamicSharedMemorySize, WSMEM_TOTAL);
    cudaFuncSetAttribute(main_gemm_kernel,
                         cudaFuncAttributeMaxDynamicSharedMemorySize, MSMEM_TOTAL);

    bias_combine_kernel<<<128, 256>>>(Wp, bv, bp);
    convert_x_kernel<<<(MMAIN * KDIM / 4 + 255) / 256, 256>>>(x, xh,
                                                              MMAIN * KDIM / 4);
    split_compact_kernel<<<(KDIM * KDIM / 4 + 255) / 256, 256>>>(Wp, wph, wpl,
                                                                 KDIM * KDIM / 4);
    wv_transpose_split_kernel<<<dim3(32, 32), 256>>>(Wv, wvth, wvtl);

    wc_gemm_kernel<<<dim3(8, 16), 256, WSMEM_TOTAL>>>(wph, wpl, wvth, wvtl, wch);
    main_gemm_kernel<<<dim3(8, 64), 256, MSMEM_TOTAL>>>(xh, wch, out);
}